// round 2
// baseline (speedup 1.0000x reference)
#include <cuda_runtime.h>
#include <cstdint>
#include <cstddef>

// Problem constants (fixed by the dataset instance)
#define IN_DIM   128
#define H_E      512     // 2*IN_DIM*SCALE
#define H_S      256     // IN_DIM*SCALE
#define OUT_HALF 128
#define N_TYPES  16
#define MAX_NODES 50000

// Scratch (allocation-free rule: __device__ globals)
__device__ float g_F [MAX_NODES * H_E];   // features @ W1e_bot          [N,512]
__device__ float g_H [MAX_NODES * H_E];   // sum over edges relu(F+T)    [N,512]
__device__ float g_Sh[MAX_NODES * H_S];   // relu(features@W1s+b1s)      [N,256]
__device__ float g_T [N_TYPES * H_E];     // e_emb@W1e_top + b1e         [16,512]
__device__ int   g_deg[MAX_NODES];

// ---------------------------------------------------------------------------
// T[t][j] = b1e[j] + sum_k e_emb[t][k] * W1e[k][j]   (rows 0..127 of W1e)
// ---------------------------------------------------------------------------
__global__ void type_table_kernel(const float* __restrict__ e_emb,
                                  const float* __restrict__ W1e,
                                  const float* __restrict__ b1e)
{
    int idx = blockIdx.x * blockDim.x + threadIdx.x;
    if (idx >= N_TYPES * H_E) return;
    int t = idx / H_E;
    int j = idx - t * H_E;
    float acc = b1e[j];
    const float* er = e_emb + t * IN_DIM;
#pragma unroll 8
    for (int k = 0; k < IN_DIM; k++)
        acc = fmaf(er[k], W1e[(size_t)k * H_E + j], acc);
    g_T[idx] = acc;
}

// ---------------------------------------------------------------------------
// Edge pass: H[dst] += relu(F[src] + T[type]), deg[dst] += 1
// One warp per edge (512 floats = 128 float4 = 4 float4/lane).
// ---------------------------------------------------------------------------
__global__ __launch_bounds__(256)
void edge_kernel(const int* __restrict__ src, const int* __restrict__ dst,
                 const int* __restrict__ typ, int E)
{
    __shared__ float4 sT[N_TYPES * (H_E / 4)];   // 32 KB
    for (int i = threadIdx.x; i < N_TYPES * (H_E / 4); i += blockDim.x)
        sT[i] = ((const float4*)g_T)[i];
    __syncthreads();

    const int lane = threadIdx.x & 31;
    int warp = (blockIdx.x * blockDim.x + threadIdx.x) >> 5;
    const int nwarps = (gridDim.x * blockDim.x) >> 5;

    for (int e = warp; e < E; e += nwarps) {
        const int s = src[e];
        const int d = dst[e];
        const int t = typ[e];
        const float4* Fr = (const float4*)(g_F + (size_t)s * H_E);
        float*        Hr = g_H + (size_t)d * H_E;
        const float4* Tr = sT + t * (H_E / 4);
        if (lane == 0) atomicAdd(&g_deg[d], 1);
#pragma unroll
        for (int i = 0; i < 4; i++) {
            const int j = i * 32 + lane;
            float4 a = Fr[j];
            float4 b = Tr[j];
            float4 v;
            v.x = fmaxf(a.x + b.x, 0.f);
            v.y = fmaxf(a.y + b.y, 0.f);
            v.z = fmaxf(a.z + b.z, 0.f);
            v.w = fmaxf(a.w + b.w, 0.f);
            asm volatile("red.global.add.v4.f32 [%0], {%1,%2,%3,%4};"
                         :: "l"(Hr + j * 4), "f"(v.x), "f"(v.y), "f"(v.z), "f"(v.w)
                         : "memory");
        }
    }
}

// ---------------------------------------------------------------------------
// Tiled fp32 GEMM: C[M,N] = A[M,K] @ B[K,N] (+bias) (+rowcnt[m]*rowvec[n]) (relu)
// BM=BN=128, BK=16, 256 threads, 8x8 microtile.
// ---------------------------------------------------------------------------
template<bool RELU>
__global__ __launch_bounds__(256)
void gemm128(const float* __restrict__ A, const float* __restrict__ B,
             float* __restrict__ C, int M, int K, int N, int ldc,
             const float* __restrict__ bias,
             const int* __restrict__ rowcnt, const float* __restrict__ rowvec)
{
    __shared__ float As[16][128];   // transposed A tile: As[k][m]
    __shared__ float Bs[16][128];

    const int bm = blockIdx.x * 128;
    const int bn = blockIdx.y * 128;
    const int tid = threadIdx.x;
    const int tx = tid & 15;
    const int ty = tid >> 4;

    float acc[8][8];
#pragma unroll
    for (int i = 0; i < 8; i++)
#pragma unroll
        for (int j = 0; j < 8; j++) acc[i][j] = 0.f;

    const int rowA = tid >> 2;          // 0..63 (two halves)
    const int colA = (tid & 3) << 2;    // 0,4,8,12
    const int rowB = tid >> 5;          // 0..7 (two halves)
    const int colB = (tid & 31) << 2;   // 0..124

    for (int k0 = 0; k0 < K; k0 += 16) {
#pragma unroll
        for (int h = 0; h < 2; h++) {
            const int r = rowA + h * 64;
            const int gr = bm + r;
            float4 a4 = make_float4(0.f, 0.f, 0.f, 0.f);
            if (gr < M) a4 = *(const float4*)(A + (size_t)gr * K + (k0 + colA));
            As[colA + 0][r] = a4.x;
            As[colA + 1][r] = a4.y;
            As[colA + 2][r] = a4.z;
            As[colA + 3][r] = a4.w;
        }
#pragma unroll
        for (int h = 0; h < 2; h++) {
            const int r = rowB + h * 8;
            float4 b4 = *(const float4*)(B + (size_t)(k0 + r) * N + bn + colB);
            *(float4*)&Bs[r][colB] = b4;
        }
        __syncthreads();

#pragma unroll
        for (int k = 0; k < 16; k++) {
            float a[8], b[8];
            *(float4*)&a[0] = *(const float4*)&As[k][ty * 8];
            *(float4*)&a[4] = *(const float4*)&As[k][ty * 8 + 4];
            *(float4*)&b[0] = *(const float4*)&Bs[k][tx * 8];
            *(float4*)&b[4] = *(const float4*)&Bs[k][tx * 8 + 4];
#pragma unroll
            for (int i = 0; i < 8; i++)
#pragma unroll
                for (int j = 0; j < 8; j++)
                    acc[i][j] = fmaf(a[i], b[j], acc[i][j]);
        }
        __syncthreads();
    }

#pragma unroll
    for (int i = 0; i < 8; i++) {
        const int r = bm + ty * 8 + i;
        if (r >= M) continue;
        const float rc = rowcnt ? (float)rowcnt[r] : 0.f;
#pragma unroll
        for (int j0 = 0; j0 < 8; j0 += 4) {
            float4 v;
            float* vv = &v.x;
#pragma unroll
            for (int u = 0; u < 4; u++) {
                const int c = tx * 8 + j0 + u;        // local column
                float x = acc[i][j0 + u];
                if (bias)   x += bias[bn + c];
                if (rowcnt) x = fmaf(rc, rowvec[bn + c], x);
                if (RELU)   x = fmaxf(x, 0.f);
                vv[u] = x;
            }
            *(float4*)(C + (size_t)r * ldc + bn + tx * 8 + j0) = v;
        }
    }
}

// ---------------------------------------------------------------------------
extern "C" void kernel_launch(void* const* d_in, const int* in_sizes, int n_in,
                              void* d_out, int out_size)
{
    const float* features = (const float*)d_in[0];
    const int*   edge_src = (const int*)  d_in[1];
    const int*   edge_dst = (const int*)  d_in[2];
    const int*   edge_typ = (const int*)  d_in[3];
    const float* e_emb    = (const float*)d_in[4];
    const float* W1e      = (const float*)d_in[5];
    const float* b1e      = (const float*)d_in[6];
    const float* W2e      = (const float*)d_in[7];
    const float* b2e      = (const float*)d_in[8];
    const float* W1s      = (const float*)d_in[9];
    const float* b1s      = (const float*)d_in[10];
    const float* W2s      = (const float*)d_in[11];
    const float* b2s      = (const float*)d_in[12];
    float* out = (float*)d_out;

    const int n_nodes = in_sizes[0] / IN_DIM;
    const int n_edges = in_sizes[1];

    void *pH, *pDeg, *pF, *pSh;
    cudaGetSymbolAddress(&pH,  g_H);
    cudaGetSymbolAddress(&pDeg, g_deg);
    cudaGetSymbolAddress(&pF,  g_F);
    cudaGetSymbolAddress(&pSh, g_Sh);

    cudaMemsetAsync(pH,  0, (size_t)n_nodes * H_E * sizeof(float));
    cudaMemsetAsync(pDeg, 0, (size_t)n_nodes * sizeof(int));

    // 16x512 edge-type table (includes b1e)
    type_table_kernel<<<(N_TYPES * H_E + 255) / 256, 256>>>(e_emb, W1e, b1e);

    const int gm = (n_nodes + 127) / 128;

    // F = features @ W1e[128:,:]     [N,512]
    {
        dim3 grid(gm, H_E / 128);
        gemm128<false><<<grid, 256>>>(features, W1e + (size_t)IN_DIM * H_E,
                                      (float*)pF, n_nodes, IN_DIM, H_E, H_E,
                                      nullptr, nullptr, nullptr);
    }
    // Sh = relu(features @ W1s + b1s)   [N,256]
    {
        dim3 grid(gm, H_S / 128);
        gemm128<true><<<grid, 256>>>(features, W1s,
                                     (float*)pSh, n_nodes, IN_DIM, H_S, H_S,
                                     b1s, nullptr, nullptr);
    }
    // H[dst] += relu(F[src] + T[type])
    edge_kernel<<<2048, 256>>>(edge_src, edge_dst, edge_typ, n_edges);

    // out[:, 128:256] = H @ W2e + deg*b2e
    {
        dim3 grid(gm, OUT_HALF / 128);
        gemm128<false><<<grid, 256>>>((const float*)pH, W2e,
                                      out + OUT_HALF, n_nodes, H_E, OUT_HALF,
                                      2 * OUT_HALF, nullptr, g_deg, b2e);
    }
    // out[:, 0:128] = Sh @ W2s + b2s
    {
        dim3 grid(gm, OUT_HALF / 128);
        gemm128<false><<<grid, 256>>>((const float*)pSh, W2s,
                                      out, n_nodes, H_S, OUT_HALF,
                                      2 * OUT_HALF, b2s, nullptr, nullptr);
    }
}

// round 3
// speedup vs baseline: 1.0751x; 1.0751x over previous
#include <cuda_runtime.h>
#include <cstdint>
#include <cstddef>

// Problem constants (fixed by the dataset instance)
#define IN_DIM   128
#define H_E      512     // 2*IN_DIM*SCALE
#define H_S      256     // IN_DIM*SCALE
#define OUT_HALF 128
#define N_TYPES  16
#define MAX_NODES 50000
#define MAX_EDGES 400000

// Scratch (allocation-free rule: __device__ globals)
__device__ float g_F [MAX_NODES * H_E];   // features @ W1e_bot          [N,512]
__device__ float g_H [MAX_NODES * H_E];   // sum over edges relu(F+T)    [N,512]
__device__ float g_Sh[MAX_NODES * H_S];   // relu(features@W1s+b1s)      [N,256]
__device__ float g_T [N_TYPES * H_E];     // e_emb@W1e_top + b1e         [16,512]
__device__ int   g_deg[MAX_NODES];
__device__ int   g_cnt[MAX_NODES];        // histogram of dst
__device__ int   g_off[MAX_NODES + 1];    // CSR row offsets (by dst)
__device__ int   g_cur[MAX_NODES];        // scatter cursors
__device__ int   g_edges[MAX_EDGES];      // packed: src | (type << 20)

// ---------------------------------------------------------------------------
// T[t][j] = b1e[j] + sum_k e_emb[t][k] * W1e[k][j]   (rows 0..127 of W1e)
// ---------------------------------------------------------------------------
__global__ void type_table_kernel(const float* __restrict__ e_emb,
                                  const float* __restrict__ W1e,
                                  const float* __restrict__ b1e)
{
    int idx = blockIdx.x * blockDim.x + threadIdx.x;
    if (idx >= N_TYPES * H_E) return;
    int t = idx / H_E;
    int j = idx - t * H_E;
    float acc = b1e[j];
    const float* er = e_emb + t * IN_DIM;
#pragma unroll 8
    for (int k = 0; k < IN_DIM; k++)
        acc = fmaf(er[k], W1e[(size_t)k * H_E + j], acc);
    g_T[idx] = acc;
}

// ---------------------------------------------------------------------------
// CSR build: histogram -> scan -> scatter
// ---------------------------------------------------------------------------
__global__ void hist_kernel(const int* __restrict__ dst, int E)
{
    int i = blockIdx.x * blockDim.x + threadIdx.x;
    if (i < E) atomicAdd(&g_cnt[dst[i]], 1);
}

__global__ __launch_bounds__(1024)
void scan_kernel(int n)
{
    __shared__ int ssum[1024];
    const int t = threadIdx.x;
    const int chunk = (n + 1023) >> 10;
    const int b = t * chunk;
    const int e = min(n, b + chunk);
    int s = 0;
    for (int i = b; i < e; i++) s += g_cnt[i];
    ssum[t] = s;
    __syncthreads();
#pragma unroll
    for (int d = 1; d < 1024; d <<= 1) {
        int v = 0;
        if (t >= d) v = ssum[t - d];
        __syncthreads();
        if (t >= d) ssum[t] += v;
        __syncthreads();
    }
    int pre = (t == 0) ? 0 : ssum[t - 1];
    for (int i = b; i < e; i++) {
        g_off[i] = pre;
        g_cur[i] = pre;
        pre += g_cnt[i];
    }
    if (t == 1023) g_off[n] = ssum[1023];
}

__global__ void scatter_kernel(const int* __restrict__ src,
                               const int* __restrict__ dst,
                               const int* __restrict__ typ, int E)
{
    int i = blockIdx.x * blockDim.x + threadIdx.x;
    if (i >= E) return;
    int p = atomicAdd(&g_cur[dst[i]], 1);
    g_edges[p] = src[i] | (typ[i] << 20);
}

// ---------------------------------------------------------------------------
// Gather pass (no atomics): one warp per dst node.
// H[d] = sum_{e in CSR[d]} relu(F[src_e] + T[type_e]);  deg[d] = |CSR[d]|.
// Each lane owns 16 of the 512 columns (4 float4 accumulators).
// ---------------------------------------------------------------------------
__global__ __launch_bounds__(256)
void gather_kernel(int n_nodes)
{
    __shared__ float4 sT[N_TYPES * (H_E / 4)];   // 32 KB
    for (int i = threadIdx.x; i < N_TYPES * (H_E / 4); i += blockDim.x)
        sT[i] = ((const float4*)g_T)[i];
    __syncthreads();

    const int lane = threadIdx.x & 31;
    const int d = (blockIdx.x * blockDim.x + threadIdx.x) >> 5;
    if (d >= n_nodes) return;

    const int beg = g_off[d];
    const int end = g_off[d + 1];

    float4 acc[4];
#pragma unroll
    for (int i = 0; i < 4; i++) acc[i] = make_float4(0.f, 0.f, 0.f, 0.f);

    for (int e = beg; e < end; e++) {
        const int p = g_edges[e];
        const int s = p & 0xFFFFF;
        const int t = p >> 20;
        const float4* __restrict__ Fr = (const float4*)(g_F + (size_t)s * H_E);
        const float4* __restrict__ Tr = sT + t * (H_E / 4);
#pragma unroll
        for (int i = 0; i < 4; i++) {
            const int j = i * 32 + lane;
            float4 a = Fr[j];
            float4 b = Tr[j];
            acc[i].x += fmaxf(a.x + b.x, 0.f);
            acc[i].y += fmaxf(a.y + b.y, 0.f);
            acc[i].z += fmaxf(a.z + b.z, 0.f);
            acc[i].w += fmaxf(a.w + b.w, 0.f);
        }
    }

    float4* __restrict__ Hr = (float4*)(g_H + (size_t)d * H_E);
#pragma unroll
    for (int i = 0; i < 4; i++)
        Hr[i * 32 + lane] = acc[i];
    if (lane == 0) g_deg[d] = end - beg;
}

// ---------------------------------------------------------------------------
// Tiled fp32 GEMM: C[M,N] = A[M,K] @ B[K,N] (+bias) (+rowcnt[m]*rowvec[n]) (relu)
// BM=BN=128, BK=16, 256 threads, 8x8 microtile.
// ---------------------------------------------------------------------------
template<bool RELU>
__global__ __launch_bounds__(256)
void gemm128(const float* __restrict__ A, const float* __restrict__ B,
             float* __restrict__ C, int M, int K, int N, int ldc,
             const float* __restrict__ bias,
             const int* __restrict__ rowcnt, const float* __restrict__ rowvec)
{
    __shared__ float As[16][128];   // transposed A tile: As[k][m]
    __shared__ float Bs[16][128];

    const int bm = blockIdx.x * 128;
    const int bn = blockIdx.y * 128;
    const int tid = threadIdx.x;
    const int tx = tid & 15;
    const int ty = tid >> 4;

    float acc[8][8];
#pragma unroll
    for (int i = 0; i < 8; i++)
#pragma unroll
        for (int j = 0; j < 8; j++) acc[i][j] = 0.f;

    const int rowA = tid >> 2;          // 0..63 (two halves)
    const int colA = (tid & 3) << 2;    // 0,4,8,12
    const int rowB = tid >> 5;          // 0..7 (two halves)
    const int colB = (tid & 31) << 2;   // 0..124

    for (int k0 = 0; k0 < K; k0 += 16) {
#pragma unroll
        for (int h = 0; h < 2; h++) {
            const int r = rowA + h * 64;
            const int gr = bm + r;
            float4 a4 = make_float4(0.f, 0.f, 0.f, 0.f);
            if (gr < M) a4 = *(const float4*)(A + (size_t)gr * K + (k0 + colA));
            As[colA + 0][r] = a4.x;
            As[colA + 1][r] = a4.y;
            As[colA + 2][r] = a4.z;
            As[colA + 3][r] = a4.w;
        }
#pragma unroll
        for (int h = 0; h < 2; h++) {
            const int r = rowB + h * 8;
            float4 b4 = *(const float4*)(B + (size_t)(k0 + r) * N + bn + colB);
            *(float4*)&Bs[r][colB] = b4;
        }
        __syncthreads();

#pragma unroll
        for (int k = 0; k < 16; k++) {
            float a[8], b[8];
            *(float4*)&a[0] = *(const float4*)&As[k][ty * 8];
            *(float4*)&a[4] = *(const float4*)&As[k][ty * 8 + 4];
            *(float4*)&b[0] = *(const float4*)&Bs[k][tx * 8];
            *(float4*)&b[4] = *(const float4*)&Bs[k][tx * 8 + 4];
#pragma unroll
            for (int i = 0; i < 8; i++)
#pragma unroll
                for (int j = 0; j < 8; j++)
                    acc[i][j] = fmaf(a[i], b[j], acc[i][j]);
        }
        __syncthreads();
    }

#pragma unroll
    for (int i = 0; i < 8; i++) {
        const int r = bm + ty * 8 + i;
        if (r >= M) continue;
        const float rc = rowcnt ? (float)rowcnt[r] : 0.f;
#pragma unroll
        for (int j0 = 0; j0 < 8; j0 += 4) {
            float4 v;
            float* vv = &v.x;
#pragma unroll
            for (int u = 0; u < 4; u++) {
                const int c = tx * 8 + j0 + u;        // local column
                float x = acc[i][j0 + u];
                if (bias)   x += bias[bn + c];
                if (rowcnt) x = fmaf(rc, rowvec[bn + c], x);
                if (RELU)   x = fmaxf(x, 0.f);
                vv[u] = x;
            }
            *(float4*)(C + (size_t)r * ldc + bn + tx * 8 + j0) = v;
        }
    }
}

// ---------------------------------------------------------------------------
extern "C" void kernel_launch(void* const* d_in, const int* in_sizes, int n_in,
                              void* d_out, int out_size)
{
    const float* features = (const float*)d_in[0];
    const int*   edge_src = (const int*)  d_in[1];
    const int*   edge_dst = (const int*)  d_in[2];
    const int*   edge_typ = (const int*)  d_in[3];
    const float* e_emb    = (const float*)d_in[4];
    const float* W1e      = (const float*)d_in[5];
    const float* b1e      = (const float*)d_in[6];
    const float* W2e      = (const float*)d_in[7];
    const float* b2e      = (const float*)d_in[8];
    const float* W1s      = (const float*)d_in[9];
    const float* b1s      = (const float*)d_in[10];
    const float* W2s      = (const float*)d_in[11];
    const float* b2s      = (const float*)d_in[12];
    float* out = (float*)d_out;

    const int n_nodes = in_sizes[0] / IN_DIM;
    const int n_edges = in_sizes[1];

    void *pF, *pSh, *pH, *pCnt;
    cudaGetSymbolAddress(&pF,  g_F);
    cudaGetSymbolAddress(&pSh, g_Sh);
    cudaGetSymbolAddress(&pH,  g_H);
    cudaGetSymbolAddress(&pCnt, g_cnt);

    // --- CSR build (by destination) ---
    cudaMemsetAsync(pCnt, 0, (size_t)n_nodes * sizeof(int));
    hist_kernel<<<(n_edges + 255) / 256, 256>>>(edge_dst, n_edges);
    scan_kernel<<<1, 1024>>>(n_nodes);
    scatter_kernel<<<(n_edges + 255) / 256, 256>>>(edge_src, edge_dst, edge_typ, n_edges);

    // 16x512 edge-type table (includes b1e)
    type_table_kernel<<<(N_TYPES * H_E + 255) / 256, 256>>>(e_emb, W1e, b1e);

    const int gm = (n_nodes + 127) / 128;

    // F = features @ W1e[128:,:]     [N,512]
    {
        dim3 grid(gm, H_E / 128);
        gemm128<false><<<grid, 256>>>(features, W1e + (size_t)IN_DIM * H_E,
                                      (float*)pF, n_nodes, IN_DIM, H_E, H_E,
                                      nullptr, nullptr, nullptr);
    }
    // Sh = relu(features @ W1s + b1s)   [N,256]
    {
        dim3 grid(gm, H_S / 128);
        gemm128<true><<<grid, 256>>>(features, W1s,
                                     (float*)pSh, n_nodes, IN_DIM, H_S, H_S,
                                     b1s, nullptr, nullptr);
    }

    // H[d] = sum_{edges into d} relu(F[src] + T[type])   (no atomics)
    gather_kernel<<<(n_nodes * 32 + 255) / 256, 256>>>(n_nodes);

    // out[:, 128:256] = H @ W2e + deg*b2e
    {
        dim3 grid(gm, OUT_HALF / 128);
        gemm128<false><<<grid, 256>>>((const float*)pH, W2e,
                                      out + OUT_HALF, n_nodes, H_E, OUT_HALF,
                                      2 * OUT_HALF, nullptr, g_deg, b2e);
    }
    // out[:, 0:128] = Sh @ W2s + b2s
    {
        dim3 grid(gm, OUT_HALF / 128);
        gemm128<false><<<grid, 256>>>((const float*)pSh, W2s,
                                      out, n_nodes, H_S, OUT_HALF,
                                      2 * OUT_HALF, b2s, nullptr, nullptr);
    }
}